// round 1
// baseline (speedup 1.0000x reference)
#include <cuda_runtime.h>

#define PN 16800
#define ON 64
#define BN 64

// ---------------- scratch (static device arrays: allowed) ----------------
__device__ unsigned long long g_bp[BN * ON];     // packed (iou_bits<<32)|(~prior)
__device__ float g_btov[BN * PN];                // best-truth overlap per prior
__device__ unsigned char g_btidx[BN * PN];       // best-truth index per prior
__device__ float g_acc[3];                       // loss_l, loss_c, loss_landm sums
__device__ int g_cnt[2];                         // num_pos, num_pos1

// ---------------- init ----------------
__global__ void k_init() {
    int i = blockIdx.x * blockDim.x + threadIdx.x;
    if (i < BN * ON) g_bp[i] = 0xFFFFFFFFull;    // iou=0, prior=0
    if (i < 3) g_acc[i] = 0.f;
    if (i < 2) g_cnt[i] = 0;
}

// ---------------- matching: IoU, best-truth per prior, best-prior per truth ----
__global__ void __launch_bounds__(256) k_match(
    const float4* __restrict__ priors,
    const float* __restrict__ targets)
{
    const int b = blockIdx.y;
    __shared__ float tx1[ON], ty1[ON], tx2[ON], ty2[ON], ta[ON];
    __shared__ unsigned long long sbp[ON];
    const int tid = threadIdx.x;

    if (tid < ON) {
        const float* t = targets + (size_t)(b * ON + tid) * 15;
        float x1 = t[0], y1 = t[1], x2 = t[2], y2 = t[3];
        tx1[tid] = x1; ty1[tid] = y1; tx2[tid] = x2; ty2[tid] = y2;
        ta[tid] = (x2 - x1) * (y2 - y1);
        sbp[tid] = 0xFFFFFFFFull;
    }
    __syncthreads();

    const int PPT = 4;
    const int p0 = blockIdx.x * (256 * PPT) + tid;

    float px1[PPT], py1[PPT], px2[PPT], py2[PPT], pa[PPT];
    float bi[PPT], bd[PPT];
    int bo[PPT];

#pragma unroll
    for (int k = 0; k < PPT; k++) {
        int p = p0 + k * 256;
        bi[k] = 0.f; bd[k] = 1.f; bo[k] = 0;
        if (p < PN) {
            float4 q = priors[p];
            float hw = q.z * 0.5f, hh = q.w * 0.5f;
            px1[k] = q.x - hw; py1[k] = q.y - hh;
            px2[k] = q.x + hw; py2[k] = q.y + hh;
            pa[k] = (px2[k] - px1[k]) * (py2[k] - py1[k]);  // match ref fp order
        } else {
            px1[k] = 4.f; py1[k] = 4.f; px2[k] = 4.f; py2[k] = 4.f; pa[k] = 1.f;
        }
    }

    for (int o = 0; o < ON; o++) {
        float X1 = tx1[o], Y1 = ty1[o], X2 = tx2[o], Y2 = ty2[o], A = ta[o];
        unsigned long long cur = sbp[o];
        float r = __uint_as_float((unsigned)(cur >> 32));
#pragma unroll
        for (int k = 0; k < PPT; k++) {
            float w = fminf(X2, px2[k]) - fmaxf(X1, px1[k]);
            float h = fminf(Y2, py2[k]) - fmaxf(Y1, py1[k]);
            w = fmaxf(w, 0.f); h = fmaxf(h, 0.f);
            float inter = w * h;
            float den = A + pa[k] - inter;
            // best-truth per prior: inter/den > bi/bd  <=>  inter*bd > bi*den (dens>0)
            if (inter * bd[k] > bi[k] * den) { bi[k] = inter; bd[k] = den; bo[k] = o; }
            // best-prior per truth: prefiltered packed atomicMax
            if (inter > r * den) {
                int p = p0 + k * 256;
                if (p < PN) {
                    float iou = __fdiv_rn(inter, den);
                    unsigned long long key =
                        ((unsigned long long)__float_as_uint(iou) << 32) |
                        (unsigned)(0xFFFFFFFFu - (unsigned)p);
                    atomicMax(&sbp[o], key);
                }
            }
        }
    }

#pragma unroll
    for (int k = 0; k < PPT; k++) {
        int p = p0 + k * 256;
        if (p < PN) {
            g_btov[(size_t)b * PN + p] = __fdiv_rn(bi[k], bd[k]);
            g_btidx[(size_t)b * PN + p] = (unsigned char)bo[k];
        }
    }
    __syncthreads();
    if (tid < ON) atomicMax(&g_bp[b * ON + tid], sbp[tid]);
}

// ---------------- loss kernel: one block per batch ----------------
__device__ __forceinline__ float sl1(float x) {
    float a = fabsf(x);
    return a < 1.f ? 0.5f * a * a : a - 0.5f;
}
__device__ __forceinline__ float warp_sumf(float v) {
#pragma unroll
    for (int s = 16; s; s >>= 1) v += __shfl_xor_sync(0xffffffffu, v, s);
    return v;
}
__device__ __forceinline__ int warp_sumi(int v) {
#pragma unroll
    for (int s = 16; s; s >>= 1) v += __shfl_xor_sync(0xffffffffu, v, s);
    return v;
}

__global__ void __launch_bounds__(1024, 1) k_loss(
    const float* __restrict__ loc,
    const float* __restrict__ conf,
    const float* __restrict__ landm,
    const float4* __restrict__ priors,
    const float* __restrict__ targets)
{
    const int b = blockIdx.x;
    const int tid = threadIdx.x;
    const int NT = 1024;
    const int lane = tid & 31;

    extern __shared__ float sm[];
    float* s_ov = sm;                                     // PN floats (later: rank)
    unsigned char* s_id = (unsigned char*)(s_ov + PN);    // PN bytes

    __shared__ float s_t[ON * 4];
    __shared__ float s_lm[ON * 10];
    __shared__ int s_lab[ON];
    __shared__ unsigned int hist[2048];
    __shared__ float s_ll, s_llm, s_cep, s_sumgt;
    __shared__ int s_np, s_np1, s_cntgt, s_any, s_kr;
    __shared__ unsigned s_prefix;

    if (tid == 0) {
        s_ll = 0.f; s_llm = 0.f; s_cep = 0.f; s_sumgt = 0.f;
        s_np = 0; s_np1 = 0; s_cntgt = 0;
    }
    for (int i = tid; i < PN; i += NT) {
        s_ov[i] = g_btov[(size_t)b * PN + i];
        s_id[i] = g_btidx[(size_t)b * PN + i];
    }
    if (tid < ON) {
        const float* t = targets + (size_t)(b * ON + tid) * 15;
        s_t[tid * 4 + 0] = t[0]; s_t[tid * 4 + 1] = t[1];
        s_t[tid * 4 + 2] = t[2]; s_t[tid * 4 + 3] = t[3];
#pragma unroll
        for (int j = 0; j < 10; j++) s_lm[tid * 10 + j] = t[4 + j];
        s_lab[tid] = (int)t[14];
    }
    __syncthreads();

    // scatter (sequential, last-truth-wins; gathered old values pre-scatter)
    if (tid == 0) {
        unsigned js[ON]; float oldv[ON]; int vld[ON];
        int any = 0;
        for (int o = 0; o < ON; o++) {
            unsigned long long key = g_bp[b * ON + o];
            float iou = __uint_as_float((unsigned)(key >> 32));
            unsigned j = 0xFFFFFFFFu - (unsigned)(key & 0xFFFFFFFFull);
            js[o] = j;
            vld[o] = (iou >= 0.2f);
            any |= vld[o];
            oldv[o] = s_ov[j];
        }
        for (int o = 0; o < ON; o++) {
            s_ov[js[o]] = vld[o] ? 2.0f : oldv[o];
            s_id[js[o]] = (unsigned char)o;
        }
        s_any = any;
    }
    __syncthreads();
    if (!s_any) return;   // batch contributes nothing

    // per-prior losses + CE + rank score
    float ll = 0.f, llm = 0.f, cep = 0.f;
    int np = 0, np1 = 0;
    for (int p = tid; p < PN; p += NT) {
        float ov = s_ov[p];
        int o = s_id[p];
        int c = (ov < 0.35f) ? 0 : s_lab[o];
        bool pos = (c != 0);

        const float2 cc = *(const float2*)(conf + ((size_t)(b * PN + p)) * 2);
        float c0 = cc.x, c1 = cc.y;

        if (pos) {
            np++;
            float4 q = priors[p];
            float m0 = s_t[o * 4 + 0], m1 = s_t[o * 4 + 1];
            float m2 = s_t[o * 4 + 2], m3 = s_t[o * 4 + 3];
            float isx = 0.1f * q.z, isy = 0.1f * q.w;
            float gx = ((m0 + m2) * 0.5f - q.x) / isx;
            float gy = ((m1 + m3) * 0.5f - q.y) / isy;
            float gw = logf((m2 - m0) / q.z) * 5.0f;
            float gh = logf((m3 - m1) / q.w) * 5.0f;
            const float4 L = *(const float4*)(loc + ((size_t)(b * PN + p)) * 4);
            ll += sl1(L.x - gx) + sl1(L.y - gy) + sl1(L.z - gw) + sl1(L.w - gh);
            if (c > 0) {
                np1++;
                const float* D = landm + ((size_t)(b * PN + p)) * 10;
#pragma unroll
                for (int j = 0; j < 5; j++) {
                    float lx = (s_lm[o * 10 + 2 * j]     - q.x) / isx;
                    float ly = (s_lm[o * 10 + 2 * j + 1] - q.y) / isy;
                    llm += sl1(D[2 * j] - lx) + sl1(D[2 * j + 1] - ly);
                }
            }
        }
        float mx = fmaxf(c0, c1), mn = fminf(c0, c1);
        float lse = mx + log1pf(expf(mn - mx));
        float picked = pos ? c1 : c0;
        float ce = lse - picked;
        if (pos) cep += ce;
        s_ov[p] = pos ? 0.f : ce;   // rank score (all >= 0)
    }

    // block reduce
    float wll = warp_sumf(ll), wlm = warp_sumf(llm), wce = warp_sumf(cep);
    int wnp = warp_sumi(np), wnp1 = warp_sumi(np1);
    if (lane == 0) {
        atomicAdd(&s_ll, wll); atomicAdd(&s_llm, wlm); atomicAdd(&s_cep, wce);
        atomicAdd(&s_np, wnp); atomicAdd(&s_np1, wnp1);
    }
    __syncthreads();

    const int npos = s_np;
    const int k = min(7 * npos, PN - 1);

    if (tid == 0) { s_kr = k; s_prefix = 0; }
    __syncthreads();

    if (k > 0) {
        // radix select: k-th largest of rank score bits (11+11+10)
        for (int pass = 0; pass < 3; pass++) {
            int shift = (pass == 0) ? 21 : (pass == 1) ? 10 : 0;
            int nb = (pass == 2) ? 1024 : 2048;
            for (int i = tid; i < nb; i += NT) hist[i] = 0;
            __syncthreads();
            unsigned pref = s_prefix;
            for (int p = tid; p < PN; p += NT) {
                unsigned v = __float_as_uint(s_ov[p]);
                bool ok = (pass == 0) ||
                          ((v >> ((pass == 1) ? 21 : 10)) == pref);
                if (ok) atomicAdd(&hist[(v >> shift) & (nb - 1)], 1u);
            }
            __syncthreads();
            if (tid == 0) {
                int kr = s_kr;
                unsigned cum = 0; int sel = 0;
                for (int bin = nb - 1; bin >= 0; bin--) {
                    unsigned c = hist[bin];
                    if (cum + c >= (unsigned)kr) { sel = bin; break; }
                    cum += c;
                }
                s_kr = kr - (int)cum;
                s_prefix = (pref << ((pass == 2) ? 10 : 11)) | (unsigned)sel;
            }
            __syncthreads();
        }
        float tval = __uint_as_float(s_prefix);
        float ls = 0.f; int lc = 0;
        for (int p = tid; p < PN; p += NT) {
            float v = s_ov[p];
            if (v > tval) { ls += v; lc++; }
        }
        ls = warp_sumf(ls); lc = warp_sumi(lc);
        if (lane == 0) { atomicAdd(&s_sumgt, ls); atomicAdd(&s_cntgt, lc); }
        __syncthreads();
    }

    if (tid == 0) {
        float topsum = (k > 0)
            ? (s_sumgt + (float)(k - s_cntgt) * __uint_as_float(s_prefix))
            : 0.f;
        atomicAdd(&g_acc[0], s_ll);
        atomicAdd(&g_acc[1], s_cep + topsum);
        atomicAdd(&g_acc[2], s_llm);
        atomicAdd(&g_cnt[0], s_np);
        atomicAdd(&g_cnt[1], s_np1);
    }
}

// ---------------- finalize ----------------
__global__ void k_fin(float* __restrict__ out) {
    float N = fmaxf((float)g_cnt[0], 1.f);
    float N1 = fmaxf((float)g_cnt[1], 1.f);
    out[0] = g_acc[0] / N;
    out[1] = g_acc[1] / N;
    out[2] = g_acc[2] / N1;
}

// ---------------- launch ----------------
extern "C" void kernel_launch(void* const* d_in, const int* in_sizes, int n_in,
                              void* d_out, int out_size) {
    const float* loc = (const float*)d_in[0];
    const float* conf = (const float*)d_in[1];
    const float* landm = (const float*)d_in[2];
    const float4* priors = (const float4*)d_in[3];
    const float* targets = (const float*)d_in[4];
    float* out = (float*)d_out;

    const int DYN = PN * 4 + PN;  // 84000 bytes
    cudaFuncSetAttribute(k_loss, cudaFuncAttributeMaxDynamicSharedMemorySize, DYN);

    k_init<<<16, 256>>>();
    dim3 gm(17, 64);
    k_match<<<gm, 256>>>(priors, targets);
    k_loss<<<64, 1024, DYN>>>(loc, conf, landm, priors, targets);
    k_fin<<<1, 1>>>(out);
}

// round 2
// speedup vs baseline: 1.8033x; 1.8033x over previous
#include <cuda_runtime.h>

#define PN 16800
#define ON 64
#define BN 64
#define FULLMASK 0xffffffffu

// ---------------- scratch (zero at module load; k_fin re-zeroes) -------------
__device__ unsigned long long g_bp[BN * ON];   // packed (iou_bits<<32)|(0xFFFFFFFF-p); 0 == "no candidate"
__device__ float g_btov[BN * PN];
__device__ unsigned char g_btidx[BN * PN];
__device__ float g_rank[BN * PN];
__device__ float g_acc[3];                     // loss_l, loss_c, loss_landm
__device__ int g_cnt[2];                       // num_pos, num_pos1
__device__ int g_np[BN];                       // per-batch num_pos

// =================== matching kernel ===================
// grid (17, 64), 256 threads; block covers priors [bx*1024, bx*1024+1024)
__global__ void __launch_bounds__(256) k_match(
    const float4* __restrict__ priors,
    const float* __restrict__ targets)
{
    const int b = blockIdx.y;
    const int tid = threadIdx.x;
    const int lane = tid & 31;
    const int wid = tid >> 5;

    __shared__ float tx1[ON], ty1[ON], tx2[ON], ty2[ON];
    __shared__ float cX1[ON], cY1[ON], cX2[ON], cY2[ON], cA[ON];
    __shared__ int cO[ON];
    __shared__ unsigned long long sbp[ON];
    __shared__ float s_red[4][8];
    __shared__ float s_box[4];
    __shared__ int s_cnt;

    if (tid < ON) {
        const float* t = targets + (size_t)(b * ON + tid) * 15;
        tx1[tid] = t[0]; ty1[tid] = t[1]; tx2[tid] = t[2]; ty2[tid] = t[3];
        sbp[tid] = 0ull;
    }

    const int PPT = 4;
    const int p0 = blockIdx.x * (256 * PPT) + tid;

    float px1[PPT], py1[PPT], px2[PPT], py2[PPT], pa[PPT];
    float bi[PPT], bd[PPT];
    int bo[PPT];

    float l1 = 1e30f, l2 = -1e30f, l3 = 1e30f, l4 = -1e30f;
#pragma unroll
    for (int k = 0; k < PPT; k++) {
        int p = p0 + k * 256;
        bi[k] = 0.f; bd[k] = 1.f; bo[k] = 0;
        if (p < PN) {
            float4 q = priors[p];
            float hw = q.z * 0.5f, hh = q.w * 0.5f;
            px1[k] = q.x - hw; py1[k] = q.y - hh;
            px2[k] = q.x + hw; py2[k] = q.y + hh;
            pa[k] = (px2[k] - px1[k]) * (py2[k] - py1[k]);
            l1 = fminf(l1, px1[k]); l2 = fmaxf(l2, px2[k]);
            l3 = fminf(l3, py1[k]); l4 = fmaxf(l4, py2[k]);
        } else {
            px1[k] = 4.f; py1[k] = 4.f; px2[k] = 4.f; py2[k] = 4.f; pa[k] = 0.f;
        }
    }
    // block bbox reduce
#pragma unroll
    for (int s = 16; s; s >>= 1) {
        l1 = fminf(l1, __shfl_xor_sync(FULLMASK, l1, s));
        l2 = fmaxf(l2, __shfl_xor_sync(FULLMASK, l2, s));
        l3 = fminf(l3, __shfl_xor_sync(FULLMASK, l3, s));
        l4 = fmaxf(l4, __shfl_xor_sync(FULLMASK, l4, s));
    }
    if (lane == 0) { s_red[0][wid] = l1; s_red[1][wid] = l2; s_red[2][wid] = l3; s_red[3][wid] = l4; }
    __syncthreads();
    if (tid == 0) {
        float a = s_red[0][0], bmx = s_red[1][0], c = s_red[2][0], d = s_red[3][0];
        for (int w = 1; w < 8; w++) {
            a = fminf(a, s_red[0][w]); bmx = fmaxf(bmx, s_red[1][w]);
            c = fminf(c, s_red[2][w]); d = fmaxf(d, s_red[3][w]);
        }
        s_box[0] = a; s_box[1] = bmx; s_box[2] = c; s_box[3] = d;
    }
    __syncthreads();

    // warp 0: cull + compact truths (ascending o preserved)
    if (tid < 32) {
        float xmn = s_box[0], xmx = s_box[1], ymn = s_box[2], ymx = s_box[3];
        unsigned lml = (1u << tid) - 1u;
        int o1 = tid, o2 = tid + 32;
        bool k1 = (tx1[o1] < xmx) && (tx2[o1] > xmn) && (ty1[o1] < ymx) && (ty2[o1] > ymn);
        bool k2 = (tx1[o2] < xmx) && (tx2[o2] > xmn) && (ty1[o2] < ymx) && (ty2[o2] > ymn);
        unsigned m1 = __ballot_sync(FULLMASK, k1);
        unsigned m2 = __ballot_sync(FULLMASK, k2);
        int n1 = __popc(m1);
        if (k1) {
            int d = __popc(m1 & lml);
            cX1[d] = tx1[o1]; cY1[d] = ty1[o1]; cX2[d] = tx2[o1]; cY2[d] = ty2[o1];
            cA[d] = (tx2[o1] - tx1[o1]) * (ty2[o1] - ty1[o1]); cO[d] = o1;
        }
        if (k2) {
            int d = n1 + __popc(m2 & lml);
            cX1[d] = tx1[o2]; cY1[d] = ty1[o2]; cX2[d] = tx2[o2]; cY2[d] = ty2[o2];
            cA[d] = (tx2[o2] - tx1[o2]) * (ty2[o2] - ty1[o2]); cO[d] = o2;
        }
        if (tid == 0) s_cnt = n1 + __popc(m2);
    }
    __syncthreads();

    const int cnt = s_cnt;
    for (int j = 0; j < cnt; j++) {
        float X1 = cX1[j], Y1 = cY1[j], X2 = cX2[j], Y2 = cY2[j], A = cA[j];
        int oid = cO[j];
        unsigned long long cur = sbp[oid];
        float r = __uint_as_float((unsigned)(cur >> 32));

        float ci = 0.f, cd = 1.f;
        unsigned cp = 0;
        bool has = false;
#pragma unroll
        for (int k = 0; k < PPT; k++) {
            float w = fminf(X2, px2[k]) - fmaxf(X1, px1[k]);
            float h = fminf(Y2, py2[k]) - fmaxf(Y1, py1[k]);
            w = fmaxf(w, 0.f); h = fmaxf(h, 0.f);
            float inter = w * h;
            float den = A + pa[k] - inter;
            // best-truth per prior (strict > keeps first/lowest o)
            if (inter * bd[k] > bi[k] * den) { bi[k] = inter; bd[k] = den; bo[k] = oid; }
            // best-prior candidate (>= so equal-iou lower-p can still win via key)
            if (inter >= fmaxf(r * den, 1e-30f)) {
                if (!has || inter * cd > ci * den) { ci = inter; cd = den; cp = (unsigned)(p0 + k * 256); }
                has = true;
            }
        }
        unsigned anyb = __ballot_sync(FULLMASK, has);
        if (anyb) {
            unsigned long long key = 0ull;
            if (has) {
                float iou = __fdiv_rn(ci, cd);
                key = ((unsigned long long)__float_as_uint(iou) << 32) |
                      (unsigned long long)(0xFFFFFFFFu - cp);
            }
#pragma unroll
            for (int s = 16; s; s >>= 1) {
                unsigned long long o = __shfl_xor_sync(FULLMASK, key, s);
                if (o > key) key = o;
            }
            if (lane == 0 && key > cur) atomicMax(&sbp[oid], key);
        }
    }

#pragma unroll
    for (int k = 0; k < PPT; k++) {
        int p = p0 + k * 256;
        if (p < PN) {
            g_btov[(size_t)b * PN + p] = __fdiv_rn(bi[k], bd[k]);
            g_btidx[(size_t)b * PN + p] = (unsigned char)bo[k];
        }
    }
    __syncthreads();
    if (tid < ON) {
        unsigned long long v = sbp[tid];
        if (v) atomicMax(&g_bp[b * ON + tid], v);
    }
}

// =================== loss phase (per-prior) ===================
__device__ __forceinline__ float sl1(float x) {
    float a = fabsf(x);
    return a < 1.f ? 0.5f * a * a : a - 0.5f;
}
__device__ __forceinline__ float warp_sumf(float v) {
#pragma unroll
    for (int s = 16; s; s >>= 1) v += __shfl_xor_sync(FULLMASK, v, s);
    return v;
}
__device__ __forceinline__ int warp_sumi(int v) {
#pragma unroll
    for (int s = 16; s; s >>= 1) v += __shfl_xor_sync(FULLMASK, v, s);
    return v;
}

#define RNG 2100   // PN / 8

__global__ void __launch_bounds__(256) k_lossA(
    const float* __restrict__ loc,
    const float* __restrict__ conf,
    const float* __restrict__ landm,
    const float4* __restrict__ priors,
    const float* __restrict__ targets)
{
    const int b = blockIdx.y;
    const int r0 = blockIdx.x * RNG;
    const int tid = threadIdx.x;
    const int lane = tid & 31;

    __shared__ float s_ov[RNG];
    __shared__ unsigned char s_id[RNG];
    __shared__ float s_t[ON * 4];
    __shared__ float s_lm[ON * 10];
    __shared__ int s_lab[ON];
    __shared__ unsigned s_js[ON];
    __shared__ int s_vld[ON];
    __shared__ float s_oldv[ON];
    __shared__ int s_any;
    __shared__ float r_ll, r_lm, r_ce;
    __shared__ int r_np, r_np1;

    if (tid == 0) { r_ll = 0.f; r_lm = 0.f; r_ce = 0.f; r_np = 0; r_np1 = 0; }

    for (int i = tid; i < RNG; i += 256) {
        s_ov[i] = g_btov[(size_t)b * PN + r0 + i];
        s_id[i] = g_btidx[(size_t)b * PN + r0 + i];
    }
    if (tid < ON) {
        const float* t = targets + (size_t)(b * ON + tid) * 15;
        s_t[tid * 4 + 0] = t[0]; s_t[tid * 4 + 1] = t[1];
        s_t[tid * 4 + 2] = t[2]; s_t[tid * 4 + 3] = t[3];
#pragma unroll
        for (int j = 0; j < 10; j++) s_lm[tid * 10 + j] = t[4 + j];
        s_lab[tid] = (int)t[14];
        unsigned long long key = g_bp[b * ON + tid];
        s_js[tid] = 0xFFFFFFFFu - (unsigned)(key & 0xFFFFFFFFull);
        s_vld[tid] = (__uint_as_float((unsigned)(key >> 32)) >= 0.2f);
    }
    __syncthreads();

    if (tid == 0) {
        int any = 0;
        for (int o = 0; o < ON; o++) {
            any |= s_vld[o];
            unsigned j = s_js[o];
            if (j >= (unsigned)r0 && j < (unsigned)(r0 + RNG)) s_oldv[o] = s_ov[j - r0];
        }
        for (int o = 0; o < ON; o++) {
            unsigned j = s_js[o];
            if (j >= (unsigned)r0 && j < (unsigned)(r0 + RNG)) {
                s_ov[j - r0] = s_vld[o] ? 2.0f : s_oldv[o];
                s_id[j - r0] = (unsigned char)o;
            }
        }
        s_any = any;
    }
    __syncthreads();

    const int any = s_any;
    float ll = 0.f, llm = 0.f, cep = 0.f;
    int np = 0, np1 = 0;

    for (int idx = tid; idx < RNG; idx += 256) {
        const int p = r0 + idx;
        float ov = s_ov[idx];
        int o = s_id[idx];
        int c = (any && ov >= 0.35f) ? s_lab[o] : 0;
        bool pos = (c != 0);

        const float2 cc = *(const float2*)(conf + ((size_t)(b * PN + p)) * 2);
        float c0 = cc.x, c1 = cc.y;

        if (pos) {
            np++;
            float4 q = priors[p];
            float m0 = s_t[o * 4 + 0], m1 = s_t[o * 4 + 1];
            float m2 = s_t[o * 4 + 2], m3 = s_t[o * 4 + 3];
            float isx = 0.1f * q.z, isy = 0.1f * q.w;
            float gx = ((m0 + m2) * 0.5f - q.x) / isx;
            float gy = ((m1 + m3) * 0.5f - q.y) / isy;
            float gw = logf((m2 - m0) / q.z) * 5.0f;
            float gh = logf((m3 - m1) / q.w) * 5.0f;
            const float4 L = *(const float4*)(loc + ((size_t)(b * PN + p)) * 4);
            ll += sl1(L.x - gx) + sl1(L.y - gy) + sl1(L.z - gw) + sl1(L.w - gh);
            if (c > 0) {
                np1++;
                const float* D = landm + ((size_t)(b * PN + p)) * 10;
#pragma unroll
                for (int j = 0; j < 5; j++) {
                    float lx = (s_lm[o * 10 + 2 * j]     - q.x) / isx;
                    float ly = (s_lm[o * 10 + 2 * j + 1] - q.y) / isy;
                    llm += sl1(D[2 * j] - lx) + sl1(D[2 * j + 1] - ly);
                }
            }
        }
        float mx = fmaxf(c0, c1), mn = fminf(c0, c1);
        float lse = mx + log1pf(expf(mn - mx));
        float ce = lse - (pos ? c1 : c0);
        if (pos) cep += ce;
        g_rank[(size_t)b * PN + p] = pos ? 0.f : ce;
    }

    float wll = warp_sumf(ll), wlm = warp_sumf(llm), wce = warp_sumf(cep);
    int wnp = warp_sumi(np), wnp1 = warp_sumi(np1);
    if (lane == 0) {
        atomicAdd(&r_ll, wll); atomicAdd(&r_lm, wlm); atomicAdd(&r_ce, wce);
        atomicAdd(&r_np, wnp); atomicAdd(&r_np1, wnp1);
    }
    __syncthreads();
    if (tid == 0) {
        if (r_ll != 0.f) atomicAdd(&g_acc[0], r_ll);
        if (r_ce != 0.f) atomicAdd(&g_acc[1], r_ce);
        if (r_lm != 0.f) atomicAdd(&g_acc[2], r_lm);
        if (r_np)  { atomicAdd(&g_cnt[0], r_np); atomicAdd(&g_np[b], r_np); }
        if (r_np1) atomicAdd(&g_cnt[1], r_np1);
    }
}

// =================== hard-negative top-k select + sum ===================
__global__ void __launch_bounds__(1024, 1) k_lossB()
{
    const int b = blockIdx.x;
    const int tid = threadIdx.x;
    const int lane = tid & 31;

    extern __shared__ float s_r[];
    __shared__ unsigned hist[256];
    __shared__ unsigned s_pref;
    __shared__ int s_kr;
    __shared__ float s_sum;
    __shared__ int s_cntgt;

    const int np = g_np[b];
    const int k = min(7 * np, PN - 1);
    if (k <= 0) return;

    for (int i = tid; i < PN; i += 1024) s_r[i] = g_rank[(size_t)b * PN + i];
    if (tid == 0) { s_pref = 0; s_kr = k; s_sum = 0.f; s_cntgt = 0; }
    __syncthreads();

    // 4-pass 8-bit radix select for the k-th largest (values >= 0 -> bits ordered)
    for (int pass = 0; pass < 4; pass++) {
        const int shift = 24 - 8 * pass;
        for (int i = tid; i < 256; i += 1024) hist[i] = 0;
        __syncthreads();
        unsigned pref = s_pref;
        for (int i = tid; i < PN; i += 1024) {
            unsigned v = __float_as_uint(s_r[i]);
            bool ok = (pass == 0) || ((v >> (shift + 8)) == pref);
            unsigned bin = (v >> shift) & 255u;
            unsigned active = __ballot_sync(FULLMASK, ok);
            if (ok) {
                unsigned peers = __match_any_sync(active, bin);
                int leader = __ffs(peers) - 1;
                if (lane == leader) atomicAdd(&hist[bin], __popc(peers));
            }
        }
        __syncthreads();
        if (tid == 0) {
            int kr = s_kr;
            unsigned cum = 0; int sel = 0;
            for (int bin = 255; bin >= 0; bin--) {
                unsigned c = hist[bin];
                if (cum + c >= (unsigned)kr) { sel = bin; break; }
                cum += c;
            }
            s_kr = kr - (int)cum;
            s_pref = (s_pref << 8) | (unsigned)sel;
        }
        __syncthreads();
    }

    const float tval = __uint_as_float(s_pref);
    float ls = 0.f; int lc = 0;
    for (int i = tid; i < PN; i += 1024) {
        float v = s_r[i];
        if (v > tval) { ls += v; lc++; }
    }
    ls = warp_sumf(ls); lc = warp_sumi(lc);
    if (lane == 0) { atomicAdd(&s_sum, ls); atomicAdd(&s_cntgt, lc); }
    __syncthreads();
    if (tid == 0)
        atomicAdd(&g_acc[1], s_sum + (float)(k - s_cntgt) * tval);
}

// =================== finalize + reset for next call ===================
__global__ void k_fin(float* __restrict__ out) {
    const int tid = threadIdx.x;
    if (tid == 0) {
        float N = fmaxf((float)g_cnt[0], 1.f);
        float N1 = fmaxf((float)g_cnt[1], 1.f);
        out[0] = g_acc[0] / N;
        out[1] = g_acc[1] / N;
        out[2] = g_acc[2] / N1;
    }
    __syncthreads();
    for (int i = tid; i < BN * ON; i += 256) g_bp[i] = 0ull;
    if (tid < 3) g_acc[tid] = 0.f;
    if (tid < 2) g_cnt[tid] = 0;
    if (tid < ON) g_np[tid] = 0;
}

// =================== launch ===================
extern "C" void kernel_launch(void* const* d_in, const int* in_sizes, int n_in,
                              void* d_out, int out_size) {
    const float* loc = (const float*)d_in[0];
    const float* conf = (const float*)d_in[1];
    const float* landm = (const float*)d_in[2];
    const float4* priors = (const float4*)d_in[3];
    const float* targets = (const float*)d_in[4];
    float* out = (float*)d_out;

    cudaFuncSetAttribute(k_lossB, cudaFuncAttributeMaxDynamicSharedMemorySize, PN * 4);

    dim3 gm(17, BN);
    k_match<<<gm, 256>>>(priors, targets);
    dim3 ga(8, BN);
    k_lossA<<<ga, 256>>>(loc, conf, landm, priors, targets);
    k_lossB<<<BN, 1024, PN * 4>>>();
    k_fin<<<1, 256>>>(out);
}

// round 3
// speedup vs baseline: 1.8840x; 1.0448x over previous
#include <cuda_runtime.h>

#define PN 16800
#define ON 64
#define BN 64
#define FULLMASK 0xffffffffu

// ---------------- scratch (zero at module load; k_loss resets each call) ----
__device__ unsigned long long g_bp[BN * ON];   // packed (iou_bits<<32)|(0xFFFFFFFF-p)
__device__ float g_btov[BN * PN];
__device__ unsigned char g_btidx[BN * PN];
__device__ float g_acc[3];
__device__ int g_cnt[2];
__device__ int g_done;

// =================== matching kernel (separable IoU) ===================
// grid (20, 64): bx 0-6 -> grid0 (f=80,s=16), 7-13 -> grid1 (80,32),
// 14-15 -> grid2 (40,64), 16-17 -> grid3 (40,128), 18 -> grid4 (20,256),
// 19 -> grid5 (20,512). Each block covers 1024 linear cells of its grid.
__global__ void __launch_bounds__(256) k_match(
    const float4* __restrict__ priors,
    const float* __restrict__ targets)
{
    const int b = blockIdx.y;
    const int bx = blockIdx.x;
    const int tid = threadIdx.x;
    const int lane = tid & 31;
    const int wid = tid >> 5;

    int g, blk;
    if (bx < 7)       { g = 0; blk = bx; }
    else if (bx < 14) { g = 1; blk = bx - 7; }
    else if (bx < 16) { g = 2; blk = bx - 14; }
    else if (bx < 18) { g = 3; blk = bx - 16; }
    else if (bx == 18){ g = 4; blk = 0; }
    else              { g = 5; blk = 0; }
    const int f    = (g < 2) ? 80 : (g < 4) ? 40 : 20;
    const int base = (g == 0) ? 0 : (g == 1) ? 6400 : (g == 2) ? 12800 :
                     (g == 3) ? 14400 : (g == 4) ? 16000 : 16400;
    const int off  = blk * 1024;
    const int n    = min(1024, f * f - off);
    const int i0   = off / f;
    const int nrows = (off + n - 1) / f - i0 + 1;   // <= 26

    __shared__ float s_wx[ON * 80];
    __shared__ float s_wy[ON * 28];                 // col 27 = zero pad
    __shared__ float s_px1[80], s_px2[80], s_dx[80];
    __shared__ float s_py1[28], s_py2[28], s_dy[28];
    __shared__ float tX1[ON], tX2[ON], tY1[ON], tY2[ON], tA[ON];
    __shared__ float cA[ON];
    __shared__ int   cO[ON];
    __shared__ int   s_cnt;
    __shared__ unsigned long long sbp[ON], s_ini[ON];

    if (tid < ON) {
        const float* t = targets + (size_t)(b * ON + tid) * 15;
        float x1 = t[0], y1 = t[1], x2 = t[2], y2 = t[3];
        tX1[tid] = x1; tY1[tid] = y1; tX2[tid] = x2; tY2[tid] = y2;
        tA[tid] = (x2 - x1) * (y2 - y1);
        unsigned long long v = g_bp[b * ON + tid];   // warm prefilter
        sbp[tid] = v; s_ini[tid] = v;
    }
    if (tid >= 64 && tid < 144) {
        int j = tid - 64;
        if (j < f) {
            float4 q = priors[base + j];
            float a = q.x - q.z * 0.5f, c = q.x + q.z * 0.5f;
            s_px1[j] = a; s_px2[j] = c; s_dx[j] = c - a;
        }
    }
    if (tid >= 160 && tid < 192) {
        int r = tid - 160;
        if (r < nrows) {
            float4 q = priors[base + (i0 + r) * f];
            float a = q.y - q.w * 0.5f, c = q.y + q.w * 0.5f;
            s_py1[r] = a; s_py2[r] = c; s_dy[r] = c - a;
        }
    }
    __syncthreads();

    // wx[o][j], wy[o][r] precompute (identical fp formula to reference)
    for (int o = wid; o < ON; o += 8) {
        float X1 = tX1[o], X2 = tX2[o];
        for (int j = lane; j < f; j += 32)
            s_wx[o * 80 + j] = fmaxf(fminf(X2, s_px2[j]) - fmaxf(X1, s_px1[j]), 0.f);
        float Y1 = tY1[o], Y2 = tY2[o];
        if (lane < 28)
            s_wy[o * 28 + lane] = (lane < nrows)
                ? fmaxf(fminf(Y2, s_py2[lane]) - fmaxf(Y1, s_py1[lane]), 0.f)
                : 0.f;
    }
    __syncthreads();

    // compact truths overlapping the block's y-span (ascending o preserved)
    if (tid < 32) {
        float ylo = s_py1[0], yhi = s_py2[nrows - 1];
        unsigned lml = (1u << tid) - 1u;
        int o1 = tid, o2 = tid + 32;
        bool k1 = (tY1[o1] < yhi) && (tY2[o1] > ylo);
        bool k2 = (tY1[o2] < yhi) && (tY2[o2] > ylo);
        unsigned m1 = __ballot_sync(FULLMASK, k1);
        unsigned m2 = __ballot_sync(FULLMASK, k2);
        int n1 = __popc(m1);
        if (k1) { int d = __popc(m1 & lml); cO[d] = o1; cA[d] = tA[o1]; }
        if (k2) { int d = n1 + __popc(m2 & lml); cO[d] = o2; cA[d] = tA[o2]; }
        if (tid == 0) s_cnt = n1 + __popc(m2);
    }
    __syncthreads();

    // per-thread prior setup (4 priors, padded ones point at wy zero pad)
    int jj4[4], rr4[4], pg[4];
    float pa[4], bi[4], bd[4];
    int bo[4];
#pragma unroll
    for (int k = 0; k < 4; k++) {
        bi[k] = 0.f; bd[k] = 1.f; bo[k] = 0;
        int l = tid + k * 256;
        if (l < n) {
            int gi = off + l;
            int i = gi / f;
            int j = gi - i * f;
            rr4[k] = i - i0; jj4[k] = j;
            pa[k] = s_dx[j] * s_dy[i - i0];
            pg[k] = base + gi;
        } else {
            rr4[k] = 27; jj4[k] = 0; pa[k] = 0.f; pg[k] = 0;
        }
    }

    const int cnt = s_cnt;
    for (int c = 0; c < cnt; c++) {
        const int oid = cO[c];
        const float A = cA[c];
        const unsigned long long cur = sbp[oid];
        const float rth = __uint_as_float((unsigned)(cur >> 32));
        const float* wxo = s_wx + oid * 80;
        const float* wyo = s_wy + oid * 28;

        float ci = 0.f, cd = 1.f;
        unsigned cp = 0;
        bool has = false;
#pragma unroll
        for (int k = 0; k < 4; k++) {
            float inter = wxo[jj4[k]] * wyo[rr4[k]];
            float den = (A + pa[k]) - inter;
            if (inter * bd[k] > bi[k] * den) { bi[k] = inter; bd[k] = den; bo[k] = oid; }
            if (inter >= fmaxf(rth * den, 1e-30f)) {
                if (!has || inter * cd > ci * den) { ci = inter; cd = den; cp = (unsigned)pg[k]; }
                has = true;
            }
        }
        unsigned anyb = __ballot_sync(FULLMASK, has);
        if (anyb) {
            unsigned long long key = 0ull;
            if (has)
                key = ((unsigned long long)__float_as_uint(__fdiv_rn(ci, cd)) << 32) |
                      (unsigned long long)(0xFFFFFFFFu - cp);
#pragma unroll
            for (int s = 16; s; s >>= 1) {
                unsigned long long o2 = __shfl_xor_sync(FULLMASK, key, s);
                if (o2 > key) key = o2;
            }
            if (lane == 0 && key > cur) atomicMax(&sbp[oid], key);
        }
    }

#pragma unroll
    for (int k = 0; k < 4; k++) {
        int l = tid + k * 256;
        if (l < n) {
            g_btov[(size_t)b * PN + pg[k]] = __fdiv_rn(bi[k], bd[k]);
            g_btidx[(size_t)b * PN + pg[k]] = (unsigned char)bo[k];
        }
    }
    __syncthreads();
    if (tid < ON) {
        unsigned long long v = sbp[tid];
        if (v > s_ini[tid]) atomicMax(&g_bp[b * ON + tid], v);
    }
}

// =================== fused loss kernel: 1 block per batch ===================
__device__ __forceinline__ float sl1(float x) {
    float a = fabsf(x);
    return a < 1.f ? 0.5f * a * a : a - 0.5f;
}
__device__ __forceinline__ float warp_sumf(float v) {
#pragma unroll
    for (int s = 16; s; s >>= 1) v += __shfl_xor_sync(FULLMASK, v, s);
    return v;
}
__device__ __forceinline__ int warp_sumi(int v) {
#pragma unroll
    for (int s = 16; s; s >>= 1) v += __shfl_xor_sync(FULLMASK, v, s);
    return v;
}

__global__ void __launch_bounds__(1024, 1) k_loss(
    const float* __restrict__ loc,
    const float* __restrict__ conf,
    const float* __restrict__ landm,
    const float4* __restrict__ priors,
    const float* __restrict__ targets,
    float* __restrict__ out)
{
    const int b = blockIdx.x;
    const int tid = threadIdx.x;
    const int lane = tid & 31;

    extern __shared__ float sm[];
    float* s_ov = sm;                                  // PN floats (later: rank)
    unsigned char* s_id = (unsigned char*)(s_ov + PN); // PN bytes

    __shared__ float s_t[ON * 4];
    __shared__ float s_lm[ON * 10];
    __shared__ int s_lab[ON];
    __shared__ unsigned hist[256];
    __shared__ float s_ll, s_llm, s_cep, s_sum;
    __shared__ int s_np, s_np1, s_cgt, s_any, s_kr;
    __shared__ unsigned s_pref;

    if (tid == 0) {
        s_ll = 0.f; s_llm = 0.f; s_cep = 0.f; s_sum = 0.f;
        s_np = 0; s_np1 = 0; s_cgt = 0;
    }
    for (int i = tid; i < PN; i += 1024) {
        s_ov[i] = g_btov[(size_t)b * PN + i];
        s_id[i] = g_btidx[(size_t)b * PN + i];
    }
    if (tid < ON) {
        const float* t = targets + (size_t)(b * ON + tid) * 15;
        s_t[tid * 4 + 0] = t[0]; s_t[tid * 4 + 1] = t[1];
        s_t[tid * 4 + 2] = t[2]; s_t[tid * 4 + 3] = t[3];
#pragma unroll
        for (int j = 0; j < 10; j++) s_lm[tid * 10 + j] = t[4 + j];
        s_lab[tid] = (int)t[14];
    }
    __syncthreads();

    // sequential scatter (last-truth-wins, gathered pre-scatter values)
    if (tid == 0) {
        unsigned js[ON]; int vld[ON]; float oldv[ON];
        int any = 0;
        for (int o = 0; o < ON; o++) {
            unsigned long long key = g_bp[b * ON + o];
            unsigned j = 0xFFFFFFFFu - (unsigned)(key & 0xFFFFFFFFull);
            js[o] = j;
            vld[o] = (__uint_as_float((unsigned)(key >> 32)) >= 0.2f);
            any |= vld[o];
            oldv[o] = (j < PN) ? s_ov[j] : 0.f;
        }
        for (int o = 0; o < ON; o++) {
            if (js[o] < PN) {
                s_ov[js[o]] = vld[o] ? 2.0f : oldv[o];
                s_id[js[o]] = (unsigned char)o;
            }
        }
        s_any = any;
    }
    __syncthreads();
    if (tid < ON) g_bp[b * ON + tid] = 0ull;   // reset for next call

    if (s_any) {
        float ll = 0.f, llm = 0.f, cep = 0.f;
        int np = 0, np1 = 0;
        for (int p = tid; p < PN; p += 1024) {
            float ov = s_ov[p];
            int o = s_id[p];
            int c = (ov < 0.35f) ? 0 : s_lab[o];
            bool pos = (c != 0);

            const float2 cc = *(const float2*)(conf + ((size_t)(b * PN + p)) * 2);
            float c0 = cc.x, c1 = cc.y;

            if (pos) {
                np++;
                float4 q = priors[p];
                float m0 = s_t[o * 4 + 0], m1 = s_t[o * 4 + 1];
                float m2 = s_t[o * 4 + 2], m3 = s_t[o * 4 + 3];
                float isx = 0.1f * q.z, isy = 0.1f * q.w;
                float gx = ((m0 + m2) * 0.5f - q.x) / isx;
                float gy = ((m1 + m3) * 0.5f - q.y) / isy;
                float gw = logf((m2 - m0) / q.z) * 5.0f;
                float gh = logf((m3 - m1) / q.w) * 5.0f;
                const float4 L = *(const float4*)(loc + ((size_t)(b * PN + p)) * 4);
                ll += sl1(L.x - gx) + sl1(L.y - gy) + sl1(L.z - gw) + sl1(L.w - gh);
                if (c > 0) {
                    np1++;
                    const float* D = landm + ((size_t)(b * PN + p)) * 10;
#pragma unroll
                    for (int j = 0; j < 5; j++) {
                        float lx = (s_lm[o * 10 + 2 * j]     - q.x) / isx;
                        float ly = (s_lm[o * 10 + 2 * j + 1] - q.y) / isy;
                        llm += sl1(D[2 * j] - lx) + sl1(D[2 * j + 1] - ly);
                    }
                }
            }
            float mx = fmaxf(c0, c1), mn = fminf(c0, c1);
            float lse = mx + log1pf(expf(mn - mx));
            float ce = lse - (pos ? c1 : c0);
            if (pos) cep += ce;
            s_ov[p] = pos ? 0.f : ce;   // rank score (>= 0)
        }
        float wll = warp_sumf(ll), wlm = warp_sumf(llm), wce = warp_sumf(cep);
        int wnp = warp_sumi(np), wnp1 = warp_sumi(np1);
        if (lane == 0) {
            atomicAdd(&s_ll, wll); atomicAdd(&s_llm, wlm); atomicAdd(&s_cep, wce);
            atomicAdd(&s_np, wnp); atomicAdd(&s_np1, wnp1);
        }
        __syncthreads();

        const int npos = s_np;
        const int k = min(7 * npos, PN - 1);
        if (tid == 0) { s_pref = 0; s_kr = k; }
        __syncthreads();

        if (k > 0) {
            // 4-pass 8-bit radix select for the k-th largest rank score
            for (int pass = 0; pass < 4; pass++) {
                const int shift = 24 - 8 * pass;
                if (tid < 256) hist[tid] = 0;
                __syncthreads();
                unsigned pref = s_pref;
                for (int i = tid; i < PN; i += 1024) {
                    unsigned v = __float_as_uint(s_ov[i]);
                    bool ok = (pass == 0) || ((v >> (shift + 8)) == pref);
                    unsigned bin = (v >> shift) & 255u;
                    unsigned active = __ballot_sync(FULLMASK, ok);
                    if (ok) {
                        unsigned peers = __match_any_sync(active, bin);
                        if (lane == __ffs(peers) - 1) atomicAdd(&hist[bin], __popc(peers));
                    }
                }
                __syncthreads();
                if (tid == 0) {
                    int kr = s_kr;
                    unsigned cum = 0; int sel = 0;
                    for (int bin = 255; bin >= 0; bin--) {
                        unsigned c = hist[bin];
                        if (cum + c >= (unsigned)kr) { sel = bin; break; }
                        cum += c;
                    }
                    s_kr = kr - (int)cum;
                    s_pref = (s_pref << 8) | (unsigned)sel;
                }
                __syncthreads();
            }
            const float tval = __uint_as_float(s_pref);
            float ls = 0.f; int lc = 0;
            for (int i = tid; i < PN; i += 1024) {
                float v = s_ov[i];
                if (v > tval) { ls += v; lc++; }
            }
            ls = warp_sumf(ls); lc = warp_sumi(lc);
            if (lane == 0) { atomicAdd(&s_sum, ls); atomicAdd(&s_cgt, lc); }
            __syncthreads();
        }

        if (tid == 0) {
            float topsum = (k > 0)
                ? (s_sum + (float)(k - s_cgt) * __uint_as_float(s_pref)) : 0.f;
            if (s_ll != 0.f) atomicAdd(&g_acc[0], s_ll);
            float lc = s_cep + topsum;
            if (lc != 0.f) atomicAdd(&g_acc[1], lc);
            if (s_llm != 0.f) atomicAdd(&g_acc[2], s_llm);
            if (s_np)  atomicAdd(&g_cnt[0], s_np);
            if (s_np1) atomicAdd(&g_cnt[1], s_np1);
        }
    }

    // ---- last-block finalize + reset ----
    __syncthreads();
    if (tid == 0) {
        __threadfence();
        int t = atomicAdd(&g_done, 1);
        if (t == BN - 1) {
            float a0 = *(volatile float*)&g_acc[0];
            float a1 = *(volatile float*)&g_acc[1];
            float a2 = *(volatile float*)&g_acc[2];
            int c0 = *(volatile int*)&g_cnt[0];
            int c1 = *(volatile int*)&g_cnt[1];
            float N  = fmaxf((float)c0, 1.f);
            float N1 = fmaxf((float)c1, 1.f);
            out[0] = a0 / N;
            out[1] = a1 / N;
            out[2] = a2 / N1;
            g_acc[0] = 0.f; g_acc[1] = 0.f; g_acc[2] = 0.f;
            g_cnt[0] = 0; g_cnt[1] = 0;
            g_done = 0;
        }
    }
}

// =================== launch ===================
extern "C" void kernel_launch(void* const* d_in, const int* in_sizes, int n_in,
                              void* d_out, int out_size) {
    const float* loc = (const float*)d_in[0];
    const float* conf = (const float*)d_in[1];
    const float* landm = (const float*)d_in[2];
    const float4* priors = (const float4*)d_in[3];
    const float* targets = (const float*)d_in[4];
    float* out = (float*)d_out;

    const int DYN = PN * 4 + PN;  // 84000 bytes
    cudaFuncSetAttribute(k_loss, cudaFuncAttributeMaxDynamicSharedMemorySize, DYN);

    dim3 gm(20, BN);
    k_match<<<gm, 256>>>(priors, targets);
    k_loss<<<BN, 1024, DYN>>>(loc, conf, landm, priors, targets, out);
}

// round 4
// speedup vs baseline: 2.5925x; 1.3761x over previous
#include <cuda_runtime.h>

#define PN 16800
#define ON 64
#define BN 64
#define FULLMASK 0xffffffffu

// ---------------- scratch ----------------
__device__ unsigned long long g_bp[BN * ON];   // packed (iou_bits<<32)|(0xFFFFFFFF-p); overwritten each call
__device__ float g_btov[BN * PN];
__device__ unsigned char g_btidx[BN * PN];
__device__ float g_acc[3];
__device__ int g_cnt[2];
__device__ int g_done;

// =================== matching kernel ===================
// grid (21, 64): bx 0-19 = best-truth tiles (separable IoU);
// bx == 20 = per-batch best-prior-per-truth (grid-separable argmax) + acc reset.
__global__ void __launch_bounds__(256) k_match(
    const float4* __restrict__ priors,
    const float* __restrict__ targets)
{
    const int b = blockIdx.y;
    const int bx = blockIdx.x;
    const int tid = threadIdx.x;
    const int lane = tid & 31;
    const int wid = tid >> 5;

    __shared__ float tX1[ON], tX2[ON], tY1[ON], tY2[ON], tA[ON];

    if (tid < ON) {
        const float* t = targets + (size_t)(b * ON + tid) * 15;
        float x1 = t[0], y1 = t[1], x2 = t[2], y2 = t[3];
        tX1[tid] = x1; tY1[tid] = y1; tX2[tid] = x2; tY2[tid] = y2;
        tA[tid] = (x2 - x1) * (y2 - y1);
    }

    if (bx == 20) {
        // ---------- best prior per truth ----------
        __shared__ float b_px1[280], b_px2[280], b_py1[280], b_py2[280];
        if (tid < 3) g_acc[tid] = 0.f;
        if (tid >= 3 && tid < 5) g_cnt[tid - 3] = 0;

        for (int t = tid; t < 280; t += 256) {
            int g = (t < 80) ? 0 : (t < 160) ? 1 : (t < 200) ? 2 : (t < 240) ? 3 : (t < 260) ? 4 : 5;
            int off = (g == 0) ? 0 : (g == 1) ? 80 : (g == 2) ? 160 : (g == 3) ? 200 : (g == 4) ? 240 : 260;
            int f = (g < 2) ? 80 : (g < 4) ? 40 : 20;
            int base = (g == 0) ? 0 : (g == 1) ? 6400 : (g == 2) ? 12800 :
                       (g == 3) ? 14400 : (g == 4) ? 16000 : 16400;
            int j = t - off;
            float4 q = priors[base + j];
            b_px1[t] = q.x - q.z * 0.5f; b_px2[t] = q.x + q.z * 0.5f;
            float4 qy = priors[base + j * f];
            b_py1[t] = qy.y - qy.w * 0.5f; b_py2[t] = qy.y + qy.w * 0.5f;
        }
        __syncthreads();

        const int GF[6]   = {80, 80, 40, 40, 20, 20};
        const int GBASE[6]= {0, 6400, 12800, 14400, 16000, 16400};
        const int GOFF[6] = {0, 80, 160, 200, 240, 260};

        for (int it = 0; it < 8; it++) {
            const int o = wid * 8 + it;
            const float X1 = tX1[o], X2 = tX2[o], Y1 = tY1[o], Y2 = tY2[o], A = tA[o];
            unsigned long long best = 0ull;
#pragma unroll
            for (int g = 0; g < 6; g++) {
                const int f = GF[g], co = GOFF[g], base = GBASE[g];
                float bwx = -1.f; int bj = lane;
                for (int j = lane; j < f; j += 32) {
                    float v = fmaxf(fminf(X2, b_px2[co + j]) - fmaxf(X1, b_px1[co + j]), 0.f);
                    if (v > bwx) { bwx = v; bj = j; }
                }
                float bwy = -1.f; int bi2 = lane;
                for (int i = lane; i < f; i += 32) {
                    float v = fmaxf(fminf(Y2, b_py2[co + i]) - fmaxf(Y1, b_py1[co + i]), 0.f);
                    if (v > bwy) { bwy = v; bi2 = i; }
                }
#pragma unroll
                for (int s = 16; s; s >>= 1) {
                    float ov = __shfl_xor_sync(FULLMASK, bwx, s);
                    int oj = __shfl_xor_sync(FULLMASK, bj, s);
                    if (ov > bwx || (ov == bwx && oj < bj)) { bwx = ov; bj = oj; }
                    float ov2 = __shfl_xor_sync(FULLMASK, bwy, s);
                    int oi = __shfl_xor_sync(FULLMASK, bi2, s);
                    if (ov2 > bwy || (ov2 == bwy && oi < bi2)) { bwy = ov2; bi2 = oi; }
                }
                float P = bwx * bwy;
                float dx = b_px2[co + bj] - b_px1[co + bj];
                float dy = b_py2[co + bi2] - b_py1[co + bi2];
                float den = (A + dx * dy) - P;
                float iou = __fdiv_rn(P, den);
                unsigned pidx = (unsigned)(base + bi2 * f + bj);
                unsigned long long key =
                    ((unsigned long long)__float_as_uint(iou) << 32) |
                    (unsigned long long)(0xFFFFFFFFu - pidx);
                if (key > best) best = key;
            }
            if (lane == 0) g_bp[b * ON + o] = best;
        }
        return;
    }

    // ---------- best truth per prior (separable IoU tiles) ----------
    int g, blk;
    if (bx < 7)       { g = 0; blk = bx; }
    else if (bx < 14) { g = 1; blk = bx - 7; }
    else if (bx < 16) { g = 2; blk = bx - 14; }
    else if (bx < 18) { g = 3; blk = bx - 16; }
    else if (bx == 18){ g = 4; blk = 0; }
    else              { g = 5; blk = 0; }
    const int f    = (g < 2) ? 80 : (g < 4) ? 40 : 20;
    const int base = (g == 0) ? 0 : (g == 1) ? 6400 : (g == 2) ? 12800 :
                     (g == 3) ? 14400 : (g == 4) ? 16000 : 16400;
    const int off  = blk * 1024;
    const int n    = min(1024, f * f - off);
    const int i0   = off / f;
    const int nrows = (off + n - 1) / f - i0 + 1;

    __shared__ float s_wx[ON * 80];
    __shared__ float s_wy[ON * 28];
    __shared__ float s_px1[80], s_px2[80], s_dx[80];
    __shared__ float s_py1[28], s_py2[28], s_dy[28];
    __shared__ float cA[ON];
    __shared__ int   cO[ON];
    __shared__ int   s_cnt;

    if (tid >= 64 && tid < 144) {
        int j = tid - 64;
        if (j < f) {
            float4 q = priors[base + j];
            float a = q.x - q.z * 0.5f, c = q.x + q.z * 0.5f;
            s_px1[j] = a; s_px2[j] = c; s_dx[j] = c - a;
        }
    }
    if (tid >= 160 && tid < 192) {
        int r = tid - 160;
        if (r < nrows) {
            float4 q = priors[base + (i0 + r) * f];
            float a = q.y - q.w * 0.5f, c = q.y + q.w * 0.5f;
            s_py1[r] = a; s_py2[r] = c; s_dy[r] = c - a;
        }
    }
    __syncthreads();

    for (int o = wid; o < ON; o += 8) {
        float X1 = tX1[o], X2 = tX2[o];
        for (int j = lane; j < f; j += 32)
            s_wx[o * 80 + j] = fmaxf(fminf(X2, s_px2[j]) - fmaxf(X1, s_px1[j]), 0.f);
        float Y1 = tY1[o], Y2 = tY2[o];
        if (lane < 28)
            s_wy[o * 28 + lane] = (lane < nrows)
                ? fmaxf(fminf(Y2, s_py2[lane]) - fmaxf(Y1, s_py1[lane]), 0.f)
                : 0.f;
    }
    __syncthreads();

    if (tid < 32) {
        float ylo = s_py1[0], yhi = s_py2[nrows - 1];
        unsigned lml = (1u << tid) - 1u;
        int o1 = tid, o2 = tid + 32;
        bool k1 = (tY1[o1] < yhi) && (tY2[o1] > ylo);
        bool k2 = (tY1[o2] < yhi) && (tY2[o2] > ylo);
        unsigned m1 = __ballot_sync(FULLMASK, k1);
        unsigned m2 = __ballot_sync(FULLMASK, k2);
        int n1 = __popc(m1);
        if (k1) { int d = __popc(m1 & lml); cO[d] = o1; cA[d] = tA[o1]; }
        if (k2) { int d = n1 + __popc(m2 & lml); cO[d] = o2; cA[d] = tA[o2]; }
        if (tid == 0) s_cnt = n1 + __popc(m2);
    }
    __syncthreads();

    int jj4[4], rr4[4], pg[4];
    float pa[4], bi[4], bd[4];
    int bo[4];
#pragma unroll
    for (int k = 0; k < 4; k++) {
        bi[k] = 0.f; bd[k] = 1.f; bo[k] = 0;
        int l = tid + k * 256;
        if (l < n) {
            int gi = off + l;
            int i = gi / f;
            int j = gi - i * f;
            rr4[k] = i - i0; jj4[k] = j;
            pa[k] = s_dx[j] * s_dy[i - i0];
            pg[k] = base + gi;
        } else {
            rr4[k] = 27; jj4[k] = 0; pa[k] = 0.f; pg[k] = 0;
        }
    }

    const int cnt = s_cnt;
    for (int c = 0; c < cnt; c++) {
        const int oid = cO[c];
        const float A = cA[c];
        const float* wxo = s_wx + oid * 80;
        const float* wyo = s_wy + oid * 28;
#pragma unroll
        for (int k = 0; k < 4; k++) {
            float inter = wxo[jj4[k]] * wyo[rr4[k]];
            float den = (A + pa[k]) - inter;
            if (inter * bd[k] > bi[k] * den) { bi[k] = inter; bd[k] = den; bo[k] = oid; }
        }
    }

#pragma unroll
    for (int k = 0; k < 4; k++) {
        int l = tid + k * 256;
        if (l < n) {
            g_btov[(size_t)b * PN + pg[k]] = __fdiv_rn(bi[k], bd[k]);
            g_btidx[(size_t)b * PN + pg[k]] = (unsigned char)bo[k];
        }
    }
}

// =================== fused loss kernel: 1 block per batch ===================
__device__ __forceinline__ float sl1(float x) {
    float a = fabsf(x);
    return a < 1.f ? 0.5f * a * a : a - 0.5f;
}
__device__ __forceinline__ float warp_sumf(float v) {
#pragma unroll
    for (int s = 16; s; s >>= 1) v += __shfl_xor_sync(FULLMASK, v, s);
    return v;
}
__device__ __forceinline__ int warp_sumi(int v) {
#pragma unroll
    for (int s = 16; s; s >>= 1) v += __shfl_xor_sync(FULLMASK, v, s);
    return v;
}

__global__ void __launch_bounds__(1024, 1) k_loss(
    const float* __restrict__ loc,
    const float* __restrict__ conf,
    const float* __restrict__ landm,
    const float4* __restrict__ priors,
    const float* __restrict__ targets,
    float* __restrict__ out)
{
    const int b = blockIdx.x;
    const int tid = threadIdx.x;
    const int lane = tid & 31;

    extern __shared__ float sm[];
    float* s_ov = sm;
    unsigned char* s_id = (unsigned char*)(s_ov + PN);

    __shared__ float s_t[ON * 4];
    __shared__ float s_lm[ON * 10];
    __shared__ int s_lab[ON];
    __shared__ unsigned long long s_keys[ON];
    __shared__ unsigned hist[256];
    __shared__ float s_ll, s_llm, s_cep, s_sum;
    __shared__ int s_np, s_np1, s_cgt, s_any, s_kr;
    __shared__ unsigned s_pref;

    if (tid == 0) {
        s_ll = 0.f; s_llm = 0.f; s_cep = 0.f; s_sum = 0.f;
        s_np = 0; s_np1 = 0; s_cgt = 0;
    }
    for (int i = tid; i < PN; i += 1024) {
        s_ov[i] = g_btov[(size_t)b * PN + i];
        s_id[i] = g_btidx[(size_t)b * PN + i];
    }
    if (tid < ON) {
        const float* t = targets + (size_t)(b * ON + tid) * 15;
        s_t[tid * 4 + 0] = t[0]; s_t[tid * 4 + 1] = t[1];
        s_t[tid * 4 + 2] = t[2]; s_t[tid * 4 + 3] = t[3];
#pragma unroll
        for (int j = 0; j < 10; j++) s_lm[tid * 10 + j] = t[4 + j];
        s_lab[tid] = (int)t[14];
        s_keys[tid] = g_bp[b * ON + tid];
    }
    __syncthreads();

    // sequential scatter (last-truth-wins, gathered pre-scatter values) — smem only
    if (tid == 0) {
        unsigned js[ON]; int vld[ON]; float oldv[ON];
        int any = 0;
        for (int o = 0; o < ON; o++) {
            unsigned long long key = s_keys[o];
            unsigned j = 0xFFFFFFFFu - (unsigned)(key & 0xFFFFFFFFull);
            js[o] = j;
            vld[o] = (__uint_as_float((unsigned)(key >> 32)) >= 0.2f);
            any |= vld[o];
            oldv[o] = s_ov[j];
        }
        for (int o = 0; o < ON; o++) {
            s_ov[js[o]] = vld[o] ? 2.0f : oldv[o];
            s_id[js[o]] = (unsigned char)o;
        }
        s_any = any;
    }
    __syncthreads();

    if (s_any) {
        float ll = 0.f, llm = 0.f, cep = 0.f;
        int np = 0, np1 = 0;
        for (int p = tid; p < PN; p += 1024) {
            float ov = s_ov[p];
            int o = s_id[p];
            int c = (ov < 0.35f) ? 0 : s_lab[o];
            bool pos = (c != 0);

            const float2 cc = *(const float2*)(conf + ((size_t)(b * PN + p)) * 2);
            float c0 = cc.x, c1 = cc.y;

            if (pos) {
                np++;
                float4 q = priors[p];
                float m0 = s_t[o * 4 + 0], m1 = s_t[o * 4 + 1];
                float m2 = s_t[o * 4 + 2], m3 = s_t[o * 4 + 3];
                float isx = 0.1f * q.z, isy = 0.1f * q.w;
                float gx = ((m0 + m2) * 0.5f - q.x) / isx;
                float gy = ((m1 + m3) * 0.5f - q.y) / isy;
                float gw = logf((m2 - m0) / q.z) * 5.0f;
                float gh = logf((m3 - m1) / q.w) * 5.0f;
                const float4 L = *(const float4*)(loc + ((size_t)(b * PN + p)) * 4);
                ll += sl1(L.x - gx) + sl1(L.y - gy) + sl1(L.z - gw) + sl1(L.w - gh);
                if (c > 0) {
                    np1++;
                    const float* D = landm + ((size_t)(b * PN + p)) * 10;
#pragma unroll
                    for (int j = 0; j < 5; j++) {
                        float lx = (s_lm[o * 10 + 2 * j]     - q.x) / isx;
                        float ly = (s_lm[o * 10 + 2 * j + 1] - q.y) / isy;
                        llm += sl1(D[2 * j] - lx) + sl1(D[2 * j + 1] - ly);
                    }
                }
            }
            float mx = fmaxf(c0, c1), mn = fminf(c0, c1);
            float lse = mx + __logf(1.f + __expf(mn - mx));   // fast CE
            float ce = lse - (pos ? c1 : c0);
            if (pos) cep += ce;
            s_ov[p] = pos ? 0.f : ce;
        }
        float wll = warp_sumf(ll), wlm = warp_sumf(llm), wce = warp_sumf(cep);
        int wnp = warp_sumi(np), wnp1 = warp_sumi(np1);
        if (lane == 0) {
            atomicAdd(&s_ll, wll); atomicAdd(&s_llm, wlm); atomicAdd(&s_cep, wce);
            atomicAdd(&s_np, wnp); atomicAdd(&s_np1, wnp1);
        }
        __syncthreads();

        const int npos = s_np;
        const int k = min(7 * npos, PN - 1);
        if (tid == 0) { s_pref = 0; s_kr = k; }
        __syncthreads();

        if (k > 0) {
            for (int pass = 0; pass < 4; pass++) {
                const int shift = 24 - 8 * pass;
                if (tid < 256) hist[tid] = 0;
                __syncthreads();
                unsigned pref = s_pref;
                for (int i = tid; i < PN; i += 1024) {
                    unsigned v = __float_as_uint(s_ov[i]);
                    bool ok = (pass == 0) || ((v >> (shift + 8)) == pref);
                    unsigned bin = (v >> shift) & 255u;
                    unsigned active = __ballot_sync(FULLMASK, ok);
                    if (ok) {
                        unsigned peers = __match_any_sync(active, bin);
                        if (lane == __ffs(peers) - 1) atomicAdd(&hist[bin], __popc(peers));
                    }
                }
                __syncthreads();
                if (tid == 0) {
                    int kr = s_kr;
                    unsigned cum = 0; int sel = 0;
                    for (int bin = 255; bin >= 0; bin--) {
                        unsigned c = hist[bin];
                        if (cum + c >= (unsigned)kr) { sel = bin; break; }
                        cum += c;
                    }
                    s_kr = kr - (int)cum;
                    s_pref = (s_pref << 8) | (unsigned)sel;
                }
                __syncthreads();
            }
            const float tval = __uint_as_float(s_pref);
            float ls = 0.f; int lc = 0;
            for (int i = tid; i < PN; i += 1024) {
                float v = s_ov[i];
                if (v > tval) { ls += v; lc++; }
            }
            ls = warp_sumf(ls); lc = warp_sumi(lc);
            if (lane == 0) { atomicAdd(&s_sum, ls); atomicAdd(&s_cgt, lc); }
            __syncthreads();
        }

        if (tid == 0) {
            float topsum = (k > 0)
                ? (s_sum + (float)(k - s_cgt) * __uint_as_float(s_pref)) : 0.f;
            if (s_ll != 0.f) atomicAdd(&g_acc[0], s_ll);
            float lc = s_cep + topsum;
            if (lc != 0.f) atomicAdd(&g_acc[1], lc);
            if (s_llm != 0.f) atomicAdd(&g_acc[2], s_llm);
            if (s_np)  atomicAdd(&g_cnt[0], s_np);
            if (s_np1) atomicAdd(&g_cnt[1], s_np1);
        }
    }

    __syncthreads();
    if (tid == 0) {
        __threadfence();
        int t = atomicAdd(&g_done, 1);
        if (t == BN - 1) {
            float a0 = *(volatile float*)&g_acc[0];
            float a1 = *(volatile float*)&g_acc[1];
            float a2 = *(volatile float*)&g_acc[2];
            int c0 = *(volatile int*)&g_cnt[0];
            int c1 = *(volatile int*)&g_cnt[1];
            out[0] = a0 / fmaxf((float)c0, 1.f);
            out[1] = a1 / fmaxf((float)c0, 1.f);
            out[2] = a2 / fmaxf((float)c1, 1.f);
            g_done = 0;
        }
    }
}

// =================== launch ===================
extern "C" void kernel_launch(void* const* d_in, const int* in_sizes, int n_in,
                              void* d_out, int out_size) {
    const float* loc = (const float*)d_in[0];
    const float* conf = (const float*)d_in[1];
    const float* landm = (const float*)d_in[2];
    const float4* priors = (const float4*)d_in[3];
    const float* targets = (const float*)d_in[4];
    float* out = (float*)d_out;

    const int DYN = PN * 4 + PN;
    cudaFuncSetAttribute(k_loss, cudaFuncAttributeMaxDynamicSharedMemorySize, DYN);

    dim3 gm(21, BN);
    k_match<<<gm, 256>>>(priors, targets);
    k_loss<<<BN, 1024, DYN>>>(loc, conf, landm, priors, targets, out);
}